// round 13
// baseline (speedup 1.0000x reference)
#include <cuda_runtime.h>
#include <cuda_fp16.h>

#define N_NODES 50000
#define N_FEAT  128
#define N_EDGES 600000
#define N_POWERS 3

// fp16 staging copy of x (halves gather traffic + L1 wavefronts).
__device__ __half g_x16[(size_t)N_NODES * N_FEAT];

// 1 if edge_index is genuinely int64 on device, 0 if int32 (JAX x64-off).
__device__ int g_idx_is64;

__global__ void __launch_bounds__(256)
convert_x_kernel(const float* __restrict__ x, const int* __restrict__ ei32)
{
    if (blockIdx.x == 0 && threadIdx.x == 0) {
        int all_zero = 1;
#pragma unroll
        for (int k = 1; k < 256; k += 2) all_zero &= (ei32[k] == 0);
        g_idx_is64 = all_zero;
    }
    const int i = (blockIdx.x * blockDim.x + threadIdx.x) * 4;
    if (i < N_NODES * N_FEAT) {
        const float4 v = *reinterpret_cast<const float4*>(x + i);
        __half2 h0 = __floats2half2_rn(v.x, v.y);
        __half2 h1 = __floats2half2_rn(v.z, v.w);
        uint2 packed;
        packed.x = *reinterpret_cast<unsigned*>(&h0);
        packed.y = *reinterpret_cast<unsigned*>(&h1);
        *reinterpret_cast<uint2*>(&g_x16[i]) = packed;
    }
}

// abs via sign-mask (LOP3 on alu pipe instead of HABS2 on fma pipe).
static __device__ __forceinline__ __half2 habs2_and(__half2 v) {
    unsigned u = *reinterpret_cast<unsigned*>(&v) & 0x7FFF7FFFu;
    return *reinterpret_cast<__half2*>(&u);
}

// Fold half2 -> float (sum of both halves).
static __device__ __forceinline__ float hfold(__half2 a) {
    return __low2float(__hadd2(a, __lowhigh2highlow(a)));
}

// Fold two half2 accumulators into one packed half2 (lane-local sums).
static __device__ __forceinline__ __half2 hfold_pack(__half2 a, __half2 b) {
    const __half2 sa = __hadd2(a, __lowhigh2highlow(a));
    const __half2 sb = __hadd2(b, __lowhigh2highlow(b));
    return __halves2half2(__low2half(sa), __low2half(sb));
}

static __device__ __forceinline__ __half2 shfl_xor_h2(__half2 v, int off) {
    unsigned u = *reinterpret_cast<unsigned*>(&v);
    u = __shfl_xor_sync(0xFFFFFFFFu, u, off);
    return *reinterpret_cast<__half2*>(&u);
}

// In-loop shared load of 4 half2 weights; volatile so ptxas cannot hoist it
// out of the loop (the whole point is NOT holding weights in registers).
static __device__ __forceinline__ void lds_w4(__half2 w[4], unsigned addr) {
    uint4 v;
    asm volatile("ld.shared.v4.u32 {%0,%1,%2,%3}, [%4];"
                 : "=r"(v.x), "=r"(v.y), "=r"(v.z), "=r"(v.w) : "r"(addr));
    *reinterpret_cast<uint4*>(w) = v;
}

// Weight smem layout: lane l (0..7) x h (0..2) x chunk (0..1) x 4 half2.
// Byte addr = l*112 + h*32 + chunk*16 (112 stride -> conflict-free LDS.128).
#define WS_BYTES (8 * 112)

// 8 lanes per edge, 8 edges per warp-iteration. Group g (0..3) handles the
// adjacent edge pair (2g, 2g+1) = streams (A, B). Lane l owns features
// [8l,8l+8) (chunk 0) and [64+8l,+8) (chunk 1); each warp LDG.128 covers
// exactly one 128B line per edge-row. Single-phase: all 8 gathers issue at
// iteration top (MLP=8). Weights live in SMEM and are re-loaded in-loop
// (6x LDS.128), freeing 24 registers -> 64 regs with MLP=8 -> 4 CTAs/SM.
__global__ void __launch_bounds__(256, 4)
adj_learn_kernel(const void* __restrict__ edge_index_raw,
                 const float* __restrict__ Wa,
                 const float* __restrict__ ba,
                 const float* __restrict__ Wb,
                 const float* __restrict__ bb,
                 float* __restrict__ out)
{
    __shared__ __align__(16) unsigned char ws[WS_BYTES];

    const int p    = blockIdx.y;
    const int tid  = threadIdx.x;
    const int lane = tid & 31;
    const int l    = lane & 7;        // lane within edge-group
    const int g    = lane >> 3;       // edge-pair slot 0..3
    const int warp = tid >> 5;
    const int warps_per_block = blockDim.x >> 5;
    const int gwarp  = blockIdx.x * warps_per_block + warp;
    const int nwarps = gridDim.x * warps_per_block;

    // Fill weight smem: 192 half2 values, one per thread t<192.
    const float* Wap = Wa + (size_t)p * (N_FEAT * 3);
    if (tid < 192) {
        const int wl = tid / 24;          // 0..7
        const int wh = (tid / 8) % 3;     // 0..2
        const int wk = tid % 8;           // 0..7
        const int feat0 = (wk < 4) ? (8 * wl + 2 * wk) : (64 + 8 * wl + 2 * (wk - 4));
        const __half2 v = __floats2half2_rn(Wap[feat0 * 3 + wh],
                                            Wap[(feat0 + 1) * 3 + wh]);
        *reinterpret_cast<__half2*>(&ws[wl * 112 + wh * 32 + (wk / 4) * 16 + (wk % 4) * 4]) = v;
    }
    __syncthreads();

    unsigned ws_base;
    {
        unsigned ptr = (unsigned)__cvta_generic_to_shared(ws);
        ws_base = ptr + (unsigned)(l * 112);
    }

    const int shift = g_idx_is64;     // 0: int32 words, 1: int64 (read low word)

    const float ba0 = ba[p * 3 + 0];
    const float ba1 = ba[p * 3 + 1];
    const float ba2 = ba[p * 3 + 2];
    const float wb0 = Wb[p * 3 + 0];
    const float wb1 = Wb[p * 3 + 1];
    const float wb2 = Wb[p * 3 + 2];
    const float bbv = bb[p];

    const int* ei32 = (const int*)edge_index_raw;
    const int  src_base = p * 2 * N_EDGES;        // element index
    const int  dst_base = src_base + N_EDGES;
    float* outp = out + (size_t)p * N_EDGES;

    const int fA = l * 8;
    const int fB = 64 + l * 8;

    const int n_sup = N_EDGES / 8;    // 75000 super-groups of 8 edges

    for (int si = gwarp; si < n_sup; si += nwarps) {
        const int e = si * 8 + 2 * g;     // first edge of this group's pair
        // Unified index path (int32 or low word of int64).
        const int sA = ei32[(size_t)(src_base + e)     << shift];
        const int sB = ei32[(size_t)(src_base + e + 1) << shift];
        const int dA = ei32[(size_t)(dst_base + e)     << shift];
        const int dB = ei32[(size_t)(dst_base + e + 1) << shift];

        const __half* rjA = &g_x16[(size_t)sA * N_FEAT];
        const __half* riA = &g_x16[(size_t)dA * N_FEAT];
        const __half* rjB = &g_x16[(size_t)sB * N_FEAT];
        const __half* riB = &g_x16[(size_t)dB * N_FEAT];

        // All 8 gathers up front (MLP = 8).
        __half2 jA0[4], jA1[4], iA0[4], iA1[4], jB0[4], jB1[4], iB0[4], iB1[4];
        *reinterpret_cast<uint4*>(jA0) = *reinterpret_cast<const uint4*>(rjA + fA);
        *reinterpret_cast<uint4*>(jA1) = *reinterpret_cast<const uint4*>(rjA + fB);
        *reinterpret_cast<uint4*>(iA0) = *reinterpret_cast<const uint4*>(riA + fA);
        *reinterpret_cast<uint4*>(iA1) = *reinterpret_cast<const uint4*>(riA + fB);
        *reinterpret_cast<uint4*>(jB0) = *reinterpret_cast<const uint4*>(rjB + fA);
        *reinterpret_cast<uint4*>(jB1) = *reinterpret_cast<const uint4*>(rjB + fB);
        *reinterpret_cast<uint4*>(iB0) = *reinterpret_cast<const uint4*>(riB + fA);
        *reinterpret_cast<uint4*>(iB1) = *reinterpret_cast<const uint4*>(riB + fB);

        __half2 a0A = __float2half2_rn(0.f), a1A = a0A, a2A = a0A;
        __half2 a0B = a0A, a1B = a0A, a2B = a0A;

        // Chunk 0 weights (12 regs, transient) + FMAs k=0..3.
        {
            __half2 w0[4], w1[4], w2c[4];
            lds_w4(w0,  ws_base +  0);
            lds_w4(w1,  ws_base + 32);
            lds_w4(w2c, ws_base + 64);
#pragma unroll
            for (int k = 0; k < 4; ++k) {
                const __half2 dhA = habs2_and(__hsub2(jA0[k], iA0[k]));
                const __half2 dhB = habs2_and(__hsub2(jB0[k], iB0[k]));
                a0A = __hfma2(dhA, w0[k],  a0A);
                a0B = __hfma2(dhB, w0[k],  a0B);
                a1A = __hfma2(dhA, w1[k],  a1A);
                a1B = __hfma2(dhB, w1[k],  a1B);
                a2A = __hfma2(dhA, w2c[k], a2A);
                a2B = __hfma2(dhB, w2c[k], a2B);
            }
        }
        // Chunk 1 weights + FMAs k=4..7.
        {
            __half2 w0[4], w1[4], w2c[4];
            lds_w4(w0,  ws_base + 16);
            lds_w4(w1,  ws_base + 48);
            lds_w4(w2c, ws_base + 80);
#pragma unroll
            for (int k = 0; k < 4; ++k) {
                const __half2 dhA = habs2_and(__hsub2(jA1[k], iA1[k]));
                const __half2 dhB = habs2_and(__hsub2(jB1[k], iB1[k]));
                a0A = __hfma2(dhA, w0[k],  a0A);
                a0B = __hfma2(dhB, w0[k],  a0B);
                a1A = __hfma2(dhA, w1[k],  a1A);
                a1B = __hfma2(dhB, w1[k],  a1B);
                a2A = __hfma2(dhA, w2c[k], a2A);
                a2B = __hfma2(dhB, w2c[k], a2B);
            }
        }

        // Fold: (h0,h1) packed as half2, h2 as fp32, per stream.
        const __half2 pkA = hfold_pack(a0A, a1A);
        const __half2 pkB = hfold_pack(a0B, a1B);
        const float   x2A = hfold(a2A);
        const float   x2B = hfold(a2B);

        // Parity-interleaved butterfly over the 8-lane group.
        const bool oddl = (lane & 1);
        __half2 pk_keep = oddl ? pkB : pkA;
        __half2 pk_send = oddl ? pkA : pkB;
        float   x2_keep = oddl ? x2B : x2A;
        float   x2_send = oddl ? x2A : x2B;

        __half2 pk = __hadd2(pk_keep, shfl_xor_h2(pk_send, 1));
        float   x2 = x2_keep + __shfl_xor_sync(0xFFFFFFFFu, x2_send, 1);
#pragma unroll
        for (int off = 2; off <= 4; off <<= 1) {
            pk = __hadd2(pk, shfl_xor_h2(pk, off));
            x2 += __shfl_xor_sync(0xFFFFFFFFu, x2, off);
        }
        // Lane 8g holds edge 2g's (h0,h1,h2); lane 8g+1 holds edge 2g+1's.

        const float y0 = __low2float(pk);
        const float y1 = __high2float(pk);
        const float h0 = fmaxf(y0 + ba0, 0.f);
        const float h1 = fmaxf(y1 + ba1, 0.f);
        const float h2 = fmaxf(x2 + ba2, 0.f);
        const float z  = h0 * wb0 + h1 * wb1 + h2 * wb2 + bbv;
        const float r  = __fdividef(1.0f, 1.0f + __expf(-z));
        // Lanes {8g, 8g+1} store edges {2g, 2g+1}: one 32B coalesced store.
        if (l < 2) outp[si * 8 + 2 * g + (lane & 1)] = r;
    }
}

extern "C" void kernel_launch(void* const* d_in, const int* in_sizes, int n_in,
                              void* d_out, int out_size)
{
    const float* x  = (const float*)d_in[0];
    const void*  ei = d_in[1];
    const float* Wa = (const float*)d_in[2];
    const float* ba = (const float*)d_in[3];
    const float* Wb = (const float*)d_in[4];
    const float* bb = (const float*)d_in[5];
    float* out = (float*)d_out;

    convert_x_kernel<<<(N_NODES * N_FEAT / 4 + 255) / 256, 256>>>(x, (const int*)ei);

    // 591 CTAs ~= one wave at 4 CTAs/SM x 148 SMs.
    dim3 grid(197, N_POWERS, 1);
    dim3 block(256, 1, 1);
    adj_learn_kernel<<<grid, block>>>(ei, Wa, ba, Wb, bb, out);
}